// round 9
// baseline (speedup 1.0000x reference)
#include <cuda_runtime.h>

// Collapsed SimpleAttention: out[b,k] = (mean_s x[b,s,:]) @ Wv[:,k] + bv[k]
// (softmax over the query axis => sum_q att[b,q,s] = 1 => Q/K/att cancel
//  exactly under the mean-pool).
//
// SINGLE kernel, NO grid-wide barrier (per-batch dataflow, R7 structure).
// R8 deltas:
//   * x is read with __ldcs (evict-first): read-once data no longer evicts
//     Wv / g_partial from L2 between graph replays -> Phase B hits L2.
//   * Consumers prefetch their Wv slice to L2 BEFORE spin-waiting, hiding
//     the (first-replay) DRAM fetch behind the wait for late producers.

#define BB     8
#define SS     2048
#define DD     1024
#define DKK    512
#define NCHUNK 74                       // stage-1 blocks per batch
#define TOTB   (NCHUNK * BB)            // 592 = 4 * 148 (one balanced wave)

__device__ float g_partial[BB * NCHUNK * DD];   // [b][chunk][d]
__device__ unsigned g_cb[BB] = {0};             // per-batch arrival counters
__device__ unsigned g_done = 0;

__device__ __forceinline__ void spin_until(unsigned* ctr, unsigned target) {
    const volatile unsigned* p = (const volatile unsigned*)ctr;
    while (*p != target) __nanosleep(32);
}

__device__ __forceinline__ void l2_prefetch(const void* p) {
    asm volatile("prefetch.global.L2 [%0];" :: "l"(p));
}

__global__ void __launch_bounds__(256, 4)
fused_kernel(const float* __restrict__ x,
             const float* __restrict__ Wv,
             const float* __restrict__ bv,
             float* __restrict__ out) {
    __shared__ float xbs[DD];           // xbar for this block's batch
    __shared__ float red[4][64];        // GEMM quarter-reduce

    const int j = blockIdx.x;           // 0..73
    const int b = blockIdx.y;           // 0..7
    const int t = threadIdx.x;

    // ======================= Stage 1: column sum of x ======================
    {
        const int d  = t * 4;
        const int r0 = (j * SS) / NCHUNK;
        const int r1 = ((j + 1) * SS) / NCHUNK;
        const int n  = r1 - r0;

        const float4* xp = reinterpret_cast<const float4*>(
            x + ((size_t)(b * SS + r0)) * DD + d);
        const size_t rs = DD / 4;

        float4 a0 = make_float4(0.f, 0.f, 0.f, 0.f);
        float4 a1 = make_float4(0.f, 0.f, 0.f, 0.f);
        float4 a2 = make_float4(0.f, 0.f, 0.f, 0.f);
        float4 a3 = make_float4(0.f, 0.f, 0.f, 0.f);

        int s = 0;
        for (; s + 8 <= n; s += 8, xp += 8 * rs) {
            const float4 v0 = __ldcs(xp + 0 * rs);
            const float4 v1 = __ldcs(xp + 1 * rs);
            const float4 v2 = __ldcs(xp + 2 * rs);
            const float4 v3 = __ldcs(xp + 3 * rs);
            const float4 v4 = __ldcs(xp + 4 * rs);
            const float4 v5 = __ldcs(xp + 5 * rs);
            const float4 v6 = __ldcs(xp + 6 * rs);
            const float4 v7 = __ldcs(xp + 7 * rs);
            a0.x += v0.x; a0.y += v0.y; a0.z += v0.z; a0.w += v0.w;
            a1.x += v1.x; a1.y += v1.y; a1.z += v1.z; a1.w += v1.w;
            a2.x += v2.x; a2.y += v2.y; a2.z += v2.z; a2.w += v2.w;
            a3.x += v3.x; a3.y += v3.y; a3.z += v3.z; a3.w += v3.w;
            a0.x += v4.x; a0.y += v4.y; a0.z += v4.z; a0.w += v4.w;
            a1.x += v5.x; a1.y += v5.y; a1.z += v5.z; a1.w += v5.w;
            a2.x += v6.x; a2.y += v6.y; a2.z += v6.z; a2.w += v6.w;
            a3.x += v7.x; a3.y += v7.y; a3.z += v7.z; a3.w += v7.w;
        }
        for (; s < n; s++, xp += rs) {
            const float4 v = __ldcs(xp);
            a0.x += v.x; a0.y += v.y; a0.z += v.z; a0.w += v.w;
        }
        a0.x += a1.x; a0.y += a1.y; a0.z += a1.z; a0.w += a1.w;
        a2.x += a3.x; a2.y += a3.y; a2.z += a3.z; a2.w += a3.w;
        a0.x += a2.x; a0.y += a2.y; a0.z += a2.z; a0.w += a2.w;

        *reinterpret_cast<float4*>(
            g_partial + ((size_t)(b * NCHUNK + j)) * DD + d) = a0;
    }
    __syncthreads();
    __threadfence();                    // release partials
    if (t == 0) atomicAdd(&g_cb[b], 1u);

    if (j >= 8) return;                 // 528 blocks done; 64 continue

    const int ktile = j;                // k range [64*ktile, 64*ktile+64)
    const int kbase = ktile * 64;

    // ===== Prefetch this block's Wv slice to L2 while producers finish =====
    // Slice: all 1024 d rows, 64 k cols (256 B per row = 2 x 128 B lines).
    // 2048 lines / 256 threads = 8 per thread.
    {
        const float* wrow = Wv + kbase + (t & 1) * 32;   // which 128B half
        const int rstart = t >> 1;                        // 0..127
#pragma unroll
        for (int r = 0; r < 8; r++)
            l2_prefetch(wrow + (size_t)(rstart + r * 128) * DKK);
        if (t < 64) l2_prefetch(bv + kbase + t);
    }

    // =============== Wait for THIS batch's 74 partials only ================
    if (t == 0) spin_until(&g_cb[b], NCHUNK);
    __syncthreads();
    __threadfence();                    // acquire

    // ========= Phase A: xbar[b][d] redundant reduce into smem ==============
    {
        const float4* p = reinterpret_cast<const float4*>(
            g_partial + (size_t)(b * NCHUNK) * DD) + t;
        const size_t cs = DD / 4;

        float4 a0 = make_float4(0.f, 0.f, 0.f, 0.f);
        float4 a1 = make_float4(0.f, 0.f, 0.f, 0.f);
        float4 a2 = make_float4(0.f, 0.f, 0.f, 0.f);
        float4 a3 = make_float4(0.f, 0.f, 0.f, 0.f);
        int c = 0;
        for (; c + 8 <= NCHUNK; c += 8) {
            const float4 v0 = p[(size_t)(c + 0) * cs];
            const float4 v1 = p[(size_t)(c + 1) * cs];
            const float4 v2 = p[(size_t)(c + 2) * cs];
            const float4 v3 = p[(size_t)(c + 3) * cs];
            const float4 v4 = p[(size_t)(c + 4) * cs];
            const float4 v5 = p[(size_t)(c + 5) * cs];
            const float4 v6 = p[(size_t)(c + 6) * cs];
            const float4 v7 = p[(size_t)(c + 7) * cs];
            a0.x += v0.x; a0.y += v0.y; a0.z += v0.z; a0.w += v0.w;
            a1.x += v1.x; a1.y += v1.y; a1.z += v1.z; a1.w += v1.w;
            a2.x += v2.x; a2.y += v2.y; a2.z += v2.z; a2.w += v2.w;
            a3.x += v3.x; a3.y += v3.y; a3.z += v3.z; a3.w += v3.w;
            a0.x += v4.x; a0.y += v4.y; a0.z += v4.z; a0.w += v4.w;
            a1.x += v5.x; a1.y += v5.y; a1.z += v5.z; a1.w += v5.w;
            a2.x += v6.x; a2.y += v6.y; a2.z += v6.z; a2.w += v6.w;
            a3.x += v7.x; a3.y += v7.y; a3.z += v7.z; a3.w += v7.w;
        }
        for (; c < NCHUNK; c++) {
            const float4 v = p[(size_t)c * cs];
            a0.x += v.x; a0.y += v.y; a0.z += v.z; a0.w += v.w;
        }
        a0.x += a1.x; a0.y += a1.y; a0.z += a1.z; a0.w += a1.w;
        a2.x += a3.x; a2.y += a3.y; a2.z += a3.z; a2.w += a3.w;
        a0.x += a2.x; a0.y += a2.y; a0.z += a2.z; a0.w += a2.w;

        const float inv = 1.0f / (float)SS;
        a0.x *= inv; a0.y *= inv; a0.z *= inv; a0.w *= inv;
        reinterpret_cast<float4*>(xbs)[t] = a0;
    }
    __syncthreads();

    // ===== Phase B: GEMM slice, 32 independent Wv loads per group ==========
    {
        const int kk = t & 63;
        const int q  = t >> 6;
        const int d0 = q * 256;
        float acc = 0.f;
#pragma unroll
        for (int g = 0; g < 8; g++) {
            const int dg = d0 + g * 32;
            float w[32];
#pragma unroll
            for (int i = 0; i < 32; i++)
                w[i] = Wv[(size_t)(dg + i) * DKK + kbase + kk];
#pragma unroll
            for (int i = 0; i < 32; i++)
                acc += w[i] * xbs[dg + i];
        }
        red[q][kk] = acc;
    }
    __syncthreads();

    if (t < 64) {
        out[(size_t)b * DKK + kbase + t] =
            red[0][t] + red[1][t] + red[2][t] + red[3][t] + bv[kbase + t];
    }

    // ================= Counter reset (last consumer block) =================
    __syncthreads();
    if (t == 0) {
        const unsigned old = atomicAdd(&g_done, 1u);
        if (old == 63u) {               // all 64 consumer blocks finished
#pragma unroll
            for (int i = 0; i < BB; i++) g_cb[i] = 0;
            g_done = 0;
            __threadfence();
        }
    }
}

// ---------------------------------------------------------------------------
// Inputs (metadata order): x, Wq, bq, Wk, bk, Wv, bv
// ---------------------------------------------------------------------------
extern "C" void kernel_launch(void* const* d_in, const int* in_sizes, int n_in,
                              void* d_out, int out_size) {
    const float* x  = (const float*)d_in[0];
    const float* Wv = (const float*)d_in[5];
    const float* bv = (const float*)d_in[6];
    float* out = (float*)d_out;

    fused_kernel<<<dim3(NCHUNK, BB), 256>>>(x, Wv, bv, out);
}